// round 8
// baseline (speedup 1.0000x reference)
#include <cuda_runtime.h>
#include <cstdint>

#define B_ 4
#define T_ 2048
#define C_ 1024
#define H_ 16
#define D_ 64
#define M_ROWS (B_ * T_)   /* 8192 */
#define KDIM   C_          /* 1024 */
#define NCOL   C_          /* 1024 */

// Scratch (allocation-free rule: __device__ globals)
__device__ float g_q[B_ * H_ * T_ * D_];
__device__ float g_k[B_ * H_ * T_ * D_];
__device__ float g_v[B_ * H_ * T_ * D_];
__device__ float g_attn[B_ * T_ * C_];

// ===========================================================================
// mma.sync tf32 helpers (A/B are .b32 regs, accum .f32)
// ===========================================================================
__device__ __forceinline__ uint32_t tf32_rna_bits(float x) {
    uint32_t r;
    asm("cvt.rna.tf32.f32 %0, %1;" : "=r"(r) : "f"(x));
    return r;
}

// D(16x8,f32) += A(16x8,tf32) * B(8x8,tf32)
__device__ __forceinline__ void mma_tf32(float* d, const uint32_t* a,
                                         const uint32_t* b) {
    asm volatile(
        "mma.sync.aligned.m16n8k8.row.col.f32.tf32.tf32.f32 "
        "{%0,%1,%2,%3}, {%4,%5,%6,%7}, {%8,%9}, {%0,%1,%2,%3};"
        : "+f"(d[0]), "+f"(d[1]), "+f"(d[2]), "+f"(d[3])
        : "r"(a[0]), "r"(a[1]), "r"(a[2]), "r"(a[3]),
          "r"(b[0]), "r"(b[1]));
}

// ===========================================================================
// 3xTF32 GEMM: out = X[M,K] @ W[N,K]^T + bias[N]
// CTA tile 128x64, 128 threads (4 warps as 2m x 2n), warp tile 64x32.
// 3 CTAs/SM (regs ~150 <= 170 cap, smem 48KB). K-chunk 16, double buffer.
// ===========================================================================
#define KC 16
#define NCHUNK (KDIM / KC)   /* 64 */
// stage: AHI 8K | ALO 8K | BHI 4K | BLO 4K = 24KB; 2 stages = 48KB
#define ST_AHI 0
#define ST_ALO 8192
#define ST_BHI 16384
#define ST_BLO 20480
#define STG_B  24576
#define GEMM_SMEM (2 * STG_B)

__global__ __launch_bounds__(128, 3)
void gemm_mma(const float* __restrict__ X, const float* __restrict__ W,
              const float* __restrict__ bias, float* __restrict__ out,
              int headsplit)
{
    extern __shared__ __align__(16) char smem[];

    const int tid  = threadIdx.x;
    const int wid  = tid >> 5;
    const int lane = tid & 31;
    const int wm   = wid >> 1;        // 0..1
    const int wn   = wid & 1;         // 0..1
    const int col0 = blockIdx.x * 64;
    const int row0 = blockIdx.y * 128;

    const float* Xp = X + (size_t)row0 * KDIM;
    const float* Wp = W + (size_t)col0 * KDIM;

    float4 ra[4], rb[2];

    auto ldg_chunk = [&](int j) {
#pragma unroll
        for (int it = 0; it < 4; it++) {
            const int v  = tid + it * 128;    // 0..511: A float4s
            const int r  = v >> 2;
            const int kq = (v & 3) * 4;
            ra[it] = *(const float4*)(Xp + (size_t)r * KDIM + j * KC + kq);
        }
#pragma unroll
        for (int it = 0; it < 2; it++) {
            const int v  = tid + it * 128;    // 0..255: B float4s
            const int r  = v >> 2;
            const int kq = (v & 3) * 4;
            rb[it] = *(const float4*)(Wp + (size_t)r * KDIM + j * KC + kq);
        }
    };

    auto sts_chunk = [&](int stg) {
        char* sbase = smem + stg * STG_B;
#pragma unroll
        for (int it = 0; it < 4; it++) {
            const int v  = tid + it * 128;
            const int r  = v >> 2;
            const int kq = (v & 3) * 4;
            const float xv[4] = {ra[it].x, ra[it].y, ra[it].z, ra[it].w};
            const int mi = r >> 4, ki = kq >> 3;
            const int rr = r & 15;
            const int reg = (rr >> 3) | (((kq >> 2) & 1) << 1);
            char* ab = sbase + (mi * 2 + ki) * 512 + ((rr & 7) << 2) * 16 + reg * 4;
#pragma unroll
            for (int q = 0; q < 4; q++) {
                const uint32_t hi = tf32_rna_bits(xv[q]);
                const uint32_t lo = tf32_rna_bits(xv[q] - __uint_as_float(hi));
                *(uint32_t*)(ab + ST_AHI + q * 16) = hi;
                *(uint32_t*)(ab + ST_ALO + q * 16) = lo;
            }
        }
#pragma unroll
        for (int it = 0; it < 2; it++) {
            const int v  = tid + it * 128;
            const int r  = v >> 2;
            const int kq = (v & 3) * 4;
            const float wv[4] = {rb[it].x, rb[it].y, rb[it].z, rb[it].w};
            const int ni = r >> 3, ki = kq >> 3;
            const int nn = r & 7;
            const int reg = (kq >> 2) & 1;
            char* bb = sbase + (ni * 2 + ki) * 256 + (nn << 2) * 8 + reg * 4;
#pragma unroll
            for (int q = 0; q < 4; q++) {
                const uint32_t hi = tf32_rna_bits(wv[q]);
                const uint32_t lo = tf32_rna_bits(wv[q] - __uint_as_float(hi));
                *(uint32_t*)(bb + ST_BHI + q * 8) = hi;
                *(uint32_t*)(bb + ST_BLO + q * 8) = lo;
            }
        }
    };

    float acc[4][4][4];
#pragma unroll
    for (int i = 0; i < 4; i++)
#pragma unroll
        for (int j = 0; j < 4; j++)
#pragma unroll
            for (int q = 0; q < 4; q++) acc[i][j][q] = 0.0f;

    ldg_chunk(0);
    sts_chunk(0);
    ldg_chunk(1);

    for (int j = 0; j < NCHUNK; ++j) {
        const int s = j & 1;
        if (j + 1 < NCHUNK) sts_chunk(s ^ 1);
        __syncthreads();
        if (j + 2 < NCHUNK) ldg_chunk(j + 2);

        const char* sbase = smem + s * STG_B;
#pragma unroll
        for (int ki = 0; ki < 2; ki++) {
            uint32_t ah[4][4], al[4][4], bh[4][2], bl[4][2];
#pragma unroll
            for (int mi = 0; mi < 4; mi++) {
                const char* ab = sbase + ((wm * 4 + mi) * 2 + ki) * 512 + lane * 16;
                *(uint4*)ah[mi] = *(const uint4*)(ab + ST_AHI);
                *(uint4*)al[mi] = *(const uint4*)(ab + ST_ALO);
            }
#pragma unroll
            for (int ni = 0; ni < 4; ni++) {
                const char* bb = sbase + ((wn * 4 + ni) * 2 + ki) * 256 + lane * 8;
                *(uint2*)bh[ni] = *(const uint2*)(bb + ST_BHI);
                *(uint2*)bl[ni] = *(const uint2*)(bb + ST_BLO);
            }
#pragma unroll
            for (int mi = 0; mi < 4; mi++)
#pragma unroll
                for (int ni = 0; ni < 4; ni++) {
                    mma_tf32(acc[mi][ni], ah[mi], bh[ni]);
                    mma_tf32(acc[mi][ni], ah[mi], bl[ni]);
                    mma_tf32(acc[mi][ni], al[mi], bh[ni]);
                }
        }
        __syncthreads();
    }

#pragma unroll
    for (int ni = 0; ni < 4; ni++) {
        const int col = col0 + wn * 32 + ni * 8 + (lane & 3) * 2;
        const float2 bv = *(const float2*)(bias + col);
#pragma unroll
        for (int mi = 0; mi < 4; mi++) {
#pragma unroll
            for (int h = 0; h < 2; h++) {
                const int row = row0 + wm * 64 + mi * 16 + (lane >> 2) + h * 8;
                float2 o;
                o.x = acc[mi][ni][h * 2 + 0] + bv.x;
                o.y = acc[mi][ni][h * 2 + 1] + bv.y;
                float* dst;
                if (headsplit) {
                    const int b = row >> 11;
                    const int t = row & (T_ - 1);
                    const int hh = col >> 6;
                    const int dd = col & 63;
                    dst = out + (size_t)b * (H_ * T_ * D_) + (size_t)hh * (T_ * D_)
                        + (size_t)t * D_ + dd;
                } else {
                    dst = out + (size_t)row * NCOL + col;
                }
                *(float2*)dst = o;
            }
        }
    }
}

// ===========================================================================
// Flash attention on mma.sync tf32.
// Br=64 (4 warps x 16 rows), Bc=64, 128 threads, 3 CTAs/SM.
// Q cached in registers as hi-only A-frags (Q-lo term dropped: adds ~2.4e-4
// rel on S, negligible after softmax). K hi/lo in smem (2-pass S), V single.
// ===========================================================================
#define FA_BC 64
#define SM_KH 0
#define SM_KL 16384
#define SM_VF 32768
#define FA_SMEM 49152

__global__ __launch_bounds__(128, 3)
void flash_mma(const float* __restrict__ Q, const float* __restrict__ K,
               const float* __restrict__ V, float* __restrict__ Out)
{
    extern __shared__ __align__(16) char fsm[];

    const int tid  = threadIdx.x;
    const int wid  = tid >> 5;         // 0..3
    const int lane = tid & 31;
    const int q    = lane & 3;
    const int r0   = lane >> 2;
    const int bh   = blockIdx.y;
    const int qt   = blockIdx.x;       // 0..31

    const float* Qb = Q + (size_t)bh * (T_ * D_) + (size_t)qt * 64 * D_;
    const float* Kb = K + (size_t)bh * (T_ * D_);
    const float* Vb = V + (size_t)bh * (T_ * D_);

    // ---- load Q A-frags (rows wid*16 + r0 / +8), hi only ----
    uint32_t qh[8][4];
    {
        const int gr = wid * 16 + r0;
#pragma unroll
        for (int ki = 0; ki < 8; ki++) {
            const int c0 = ki * 8 + q;
            qh[ki][0] = tf32_rna_bits(Qb[(size_t)gr * D_ + c0]);
            qh[ki][1] = tf32_rna_bits(Qb[(size_t)(gr + 8) * D_ + c0]);
            qh[ki][2] = tf32_rna_bits(Qb[(size_t)gr * D_ + c0 + 4]);
            qh[ki][3] = tf32_rna_bits(Qb[(size_t)(gr + 8) * D_ + c0 + 4]);
        }
    }

    float Of[8][4];
#pragma unroll
    for (int nb = 0; nb < 8; nb++)
#pragma unroll
        for (int j = 0; j < 4; j++) Of[nb][j] = 0.0f;
    float m0 = -1e30f, m1 = -1e30f, l0 = 0.0f, l1 = 0.0f;

    for (int kt = 0; kt < T_ / FA_BC; kt++) {
        __syncthreads();

        // ---- producer: frag-pack K (hi/lo) and V (single) ----
        const float* Kt = Kb + (size_t)kt * FA_BC * D_;
        const float* Vt = Vb + (size_t)kt * FA_BC * D_;
#pragma unroll
        for (int it = 0; it < 8; it++) {
            const int v  = tid + it * 128;      // 0..1023 float4
            const int n  = v >> 4;              // row 0..63
            const int d0 = (v & 15) * 4;
            const float4 kv = *(const float4*)(Kt + (size_t)n * D_ + d0);
            const float4 vv = *(const float4*)(Vt + (size_t)n * D_ + d0);
            const float kf[4] = {kv.x, kv.y, kv.z, kv.w};
            const float vf4[4] = {vv.x, vv.y, vv.z, vv.w};
            {
                char* kb = fsm + ((n >> 3) * 8 + (d0 >> 3)) * 256
                         + (n & 7) * 32 + ((d0 >> 2) & 1) * 4;
#pragma unroll
                for (int qq = 0; qq < 4; qq++) {
                    const uint32_t hi = tf32_rna_bits(kf[qq]);
                    const uint32_t lo = tf32_rna_bits(kf[qq] - __uint_as_float(hi));
                    *(uint32_t*)(kb + SM_KH + qq * 8) = hi;
                    *(uint32_t*)(kb + SM_KL + qq * 8) = lo;
                }
            }
            {
                char* vb = fsm + SM_VF + ((n >> 2) & 1) * 4 + (n & 3) * 8;
#pragma unroll
                for (int qq = 0; qq < 4; qq++) {
                    const int d = d0 + qq;
                    *(uint32_t*)(vb + ((d >> 3) * 8 + (n >> 3)) * 256
                                 + (d & 7) * 32) = tf32_rna_bits(vf4[qq]);
                }
            }
        }
        __syncthreads();

        // ---- S = Q K^T (2-pass: qh*kh + qh*kl) ----
        float S[8][4];
#pragma unroll
        for (int nb = 0; nb < 8; nb++)
#pragma unroll
            for (int j = 0; j < 4; j++) S[nb][j] = 0.0f;

#pragma unroll
        for (int ki = 0; ki < 8; ki++) {
#pragma unroll
            for (int nb = 0; nb < 8; nb++) {
                uint32_t kh2[2], kl2[2];
                const char* kb = fsm + ((nb * 8 + ki) * 256) + lane * 8;
                *(uint2*)kh2 = *(const uint2*)(kb + SM_KH);
                *(uint2*)kl2 = *(const uint2*)(kb + SM_KL);
                mma_tf32(S[nb], qh[ki], kh2);
                mma_tf32(S[nb], qh[ki], kl2);
            }
        }

        // ---- online softmax (rows r0, r0+8) ----
        float mx0 = -1e30f, mx1 = -1e30f;
#pragma unroll
        for (int nb = 0; nb < 8; nb++) {
#pragma unroll
            for (int j = 0; j < 4; j++) S[nb][j] *= 0.125f;
            mx0 = fmaxf(mx0, fmaxf(S[nb][0], S[nb][1]));
            mx1 = fmaxf(mx1, fmaxf(S[nb][2], S[nb][3]));
        }
        mx0 = fmaxf(mx0, __shfl_xor_sync(0xffffffffu, mx0, 1));
        mx0 = fmaxf(mx0, __shfl_xor_sync(0xffffffffu, mx0, 2));
        mx1 = fmaxf(mx1, __shfl_xor_sync(0xffffffffu, mx1, 1));
        mx1 = fmaxf(mx1, __shfl_xor_sync(0xffffffffu, mx1, 2));

        const float mn0 = fmaxf(m0, mx0);
        const float mn1 = fmaxf(m1, mx1);
        const float a0 = __expf(m0 - mn0);
        const float a1 = __expf(m1 - mn1);
        m0 = mn0; m1 = mn1;

        float rs0 = 0.0f, rs1 = 0.0f;
#pragma unroll
        for (int nb = 0; nb < 8; nb++) {
            S[nb][0] = __expf(S[nb][0] - mn0); rs0 += S[nb][0];
            S[nb][1] = __expf(S[nb][1] - mn0); rs0 += S[nb][1];
            S[nb][2] = __expf(S[nb][2] - mn1); rs1 += S[nb][2];
            S[nb][3] = __expf(S[nb][3] - mn1); rs1 += S[nb][3];
        }
        rs0 += __shfl_xor_sync(0xffffffffu, rs0, 1);
        rs0 += __shfl_xor_sync(0xffffffffu, rs0, 2);
        rs1 += __shfl_xor_sync(0xffffffffu, rs1, 1);
        rs1 += __shfl_xor_sync(0xffffffffu, rs1, 2);
        l0 = l0 * a0 + rs0;
        l1 = l1 * a1 + rs1;
#pragma unroll
        for (int nb = 0; nb < 8; nb++) {
            Of[nb][0] *= a0; Of[nb][1] *= a0;
            Of[nb][2] *= a1; Of[nb][3] *= a1;
        }

        // ---- O += P V ----
        const int bq = lane & ~3;
        const int s0 = bq | (q >> 1);
        const int s1 = bq | ((q >> 1) + 2);
#pragma unroll
        for (int kc = 0; kc < 8; kc++) {
            float aw[4];
            {
                const float t0 = __shfl_sync(0xffffffffu, S[kc][0], s0);
                const float t1 = __shfl_sync(0xffffffffu, S[kc][1], s0);
                aw[0] = (q & 1) ? t1 : t0;
                const float u0 = __shfl_sync(0xffffffffu, S[kc][0], s1);
                const float u1 = __shfl_sync(0xffffffffu, S[kc][1], s1);
                aw[2] = (q & 1) ? u1 : u0;
                const float v0 = __shfl_sync(0xffffffffu, S[kc][2], s0);
                const float v1 = __shfl_sync(0xffffffffu, S[kc][3], s0);
                aw[1] = (q & 1) ? v1 : v0;
                const float w0 = __shfl_sync(0xffffffffu, S[kc][2], s1);
                const float w1 = __shfl_sync(0xffffffffu, S[kc][3], s1);
                aw[3] = (q & 1) ? w1 : w0;
            }
            uint32_t ah[4], al[4];
#pragma unroll
            for (int j = 0; j < 4; j++) {
                ah[j] = tf32_rna_bits(aw[j]);
                al[j] = tf32_rna_bits(aw[j] - __uint_as_float(ah[j]));
            }
#pragma unroll
            for (int nb = 0; nb < 8; nb++) {
                uint32_t vf[2];
                *(uint2*)vf = *(const uint2*)(fsm + SM_VF
                              + ((nb * 8 + kc) * 256) + lane * 8);
                mma_tf32(Of[nb], ah, vf);
                mma_tf32(Of[nb], al, vf);
            }
        }
    }

    // ---- epilogue ----
    const int b = bh >> 4;
    const int h = bh & 15;
    const int t0r = qt * 64 + wid * 16 + r0;
    const float inv0 = 1.0f / l0;
    const float inv1 = 1.0f / l1;
#pragma unroll
    for (int nb = 0; nb < 8; nb++) {
        const int col = h * 64 + nb * 8 + 2 * q;
        float2 o;
        o.x = Of[nb][0] * inv0; o.y = Of[nb][1] * inv0;
        *(float2*)(&Out[(size_t)(b * T_ + t0r) * C_ + col]) = o;
        o.x = Of[nb][2] * inv1; o.y = Of[nb][3] * inv1;
        *(float2*)(&Out[(size_t)(b * T_ + t0r + 8) * C_ + col]) = o;
    }
}

// ---------------------------------------------------------------------------
extern "C" void kernel_launch(void* const* d_in, const int* in_sizes, int n_in,
                              void* d_out, int out_size)
{
    const float* querys = (const float*)d_in[0];
    const float* keys   = (const float*)d_in[1];
    const float* values = (const float*)d_in[2];
    const float* Wq = (const float*)d_in[3];
    const float* bq = (const float*)d_in[4];
    const float* Wk = (const float*)d_in[5];
    const float* bk = (const float*)d_in[6];
    const float* Wv = (const float*)d_in[7];
    const float* bv = (const float*)d_in[8];
    const float* Wo = (const float*)d_in[9];
    const float* bo = (const float*)d_in[10];

    float *qp, *kp, *vp, *ap;
    cudaGetSymbolAddress((void**)&qp, g_q);
    cudaGetSymbolAddress((void**)&kp, g_k);
    cudaGetSymbolAddress((void**)&vp, g_v);
    cudaGetSymbolAddress((void**)&ap, g_attn);

    cudaFuncSetAttribute(gemm_mma, cudaFuncAttributeMaxDynamicSharedMemorySize,
                         GEMM_SMEM);
    cudaFuncSetAttribute(flash_mma, cudaFuncAttributeMaxDynamicSharedMemorySize,
                         FA_SMEM);

    const dim3 gg(NCOL / 64, M_ROWS / 128);   // (16, 64)

    gemm_mma<<<gg, 128, GEMM_SMEM>>>(querys, Wq, bq, qp, 1);
    gemm_mma<<<gg, 128, GEMM_SMEM>>>(keys,   Wk, bk, kp, 1);
    gemm_mma<<<gg, 128, GEMM_SMEM>>>(values, Wv, bv, vp, 1);

    flash_mma<<<dim3(T_ / 64, B_ * H_), 128, FA_SMEM>>>(qp, kp, vp, ap);

    gemm_mma<<<gg, 128, GEMM_SMEM>>>(ap, Wo, bo, (float*)d_out, 0);
}